// round 9
// baseline (speedup 1.0000x reference)
#include <cuda_runtime.h>
#include <cuda_fp16.h>
#include <cstdint>

// ---------------- problem constants ----------------
#define BB    64
#define HH    64
#define WWID  64
#define CINC  128
#define COUTC 256
#define HOUT  62
#define WOUT  62
#define MM    3844
#define KKTOT 1152
#define NNTOT 256

// ---------------- GEMM tiling ----------------
#define BM     128
#define BN     128
#define BK     32
#define NIT    (KKTOT / BK)   // 36
#define STAGES 5
#define NTHREADS 256

// smem (halves): As[s][128][40], Bs[s][32][136]
#define A_ROW_H 40
#define B_ROW_H 136
#define A_ST_H  (BM * A_ROW_H)   // 5120 halves = 10240 B
#define B_ST_H  (BK * B_ROW_H)   // 4352 halves = 8704 B
#define SMEM_A  0
#define SMEM_B  (STAGES * A_ST_H * 2)                  // 51200
#define SMEM_TOTAL (SMEM_B + STAGES * B_ST_H * 2)      // 51200 + 43520 = 94720

// ---------------- scratch ----------------
__device__ __half g_Xh[(size_t)BB * HH * WWID * CINC];   // X fp16 NHWC
__device__ __half g_Wh[(size_t)BB * KKTOT * COUTC];      // memW fp16 [b][k][n]

// ---------------- fused prep ----------------
#define XBLOCKS 32768
#define WBLOCKS 18432
__global__ void prep_kernel(const float* __restrict__ X,
                            const float* __restrict__ W,
                            const float* __restrict__ Werr) {
    if (blockIdx.x < XBLOCKS) {
        size_t i = ((size_t)blockIdx.x * blockDim.x + threadIdx.x) * 4;
        float4 v = *reinterpret_cast<const float4*>(X + i);
        __half2 h0 = __floats2half2_rn(v.x, v.y);
        __half2 h1 = __floats2half2_rn(v.z, v.w);
        uint2 o;
        o.x = *reinterpret_cast<uint32_t*>(&h0);
        o.y = *reinterpret_cast<uint32_t*>(&h1);
        *reinterpret_cast<uint2*>(g_Xh + i) = o;
    } else {
        size_t i = ((size_t)(blockIdx.x - XBLOCKS) * blockDim.x + threadIdx.x) * 4;
        size_t wi = i % ((size_t)KKTOT * COUTC);
        float4 w = *reinterpret_cast<const float4*>(W + wi);
        float4 e = *reinterpret_cast<const float4*>(Werr + i);
        __half2 h0 = __floats2half2_rn(w.x * e.x, w.y * e.y);
        __half2 h1 = __floats2half2_rn(w.z * e.z, w.w * e.w);
        uint2 o;
        o.x = *reinterpret_cast<uint32_t*>(&h0);
        o.y = *reinterpret_cast<uint32_t*>(&h1);
        *reinterpret_cast<uint2*>(g_Wh + i) = o;
    }
}

// ---------------- PTX helpers ----------------
__device__ __forceinline__ void cp16(uint32_t dst, const void* src) {
    asm volatile("cp.async.cg.shared.global [%0], [%1], 16;\n" :: "r"(dst), "l"(src));
}
__device__ __forceinline__ void cp_commit() {
    asm volatile("cp.async.commit_group;\n" ::: "memory");
}
template <int N>
__device__ __forceinline__ void cp_wait() {
    asm volatile("cp.async.wait_group %0;\n" :: "n"(N) : "memory");
}
__device__ __forceinline__ void ldmatrix_x4(uint32_t* r, uint32_t addr) {
    asm volatile("ldmatrix.sync.aligned.m8n8.x4.shared.b16 {%0,%1,%2,%3}, [%4];\n"
                 : "=r"(r[0]), "=r"(r[1]), "=r"(r[2]), "=r"(r[3]) : "r"(addr));
}
__device__ __forceinline__ void ldmatrix_x4_trans(uint32_t* r, uint32_t addr) {
    asm volatile("ldmatrix.sync.aligned.m8n8.x4.trans.shared.b16 {%0,%1,%2,%3}, [%4];\n"
                 : "=r"(r[0]), "=r"(r[1]), "=r"(r[2]), "=r"(r[3]) : "r"(addr));
}
__device__ __forceinline__ void mma16816(float* c, const uint32_t* a, const uint32_t* b) {
    asm volatile(
        "mma.sync.aligned.m16n8k16.row.col.f32.f16.f16.f32 "
        "{%0,%1,%2,%3}, {%4,%5,%6,%7}, {%8,%9}, {%0,%1,%2,%3};\n"
        : "+f"(c[0]), "+f"(c[1]), "+f"(c[2]), "+f"(c[3])
        : "r"(a[0]), "r"(a[1]), "r"(a[2]), "r"(a[3]), "r"(b[0]), "r"(b[1]));
}

// ---------------- main GEMM ----------------
// grid (2, 31, 64), 256 threads (2x4 warps, warp tile 64x32)
// 5-stage cp.async ring (wait<3>), staggered LDSM/MMA.
__global__ __launch_bounds__(NTHREADS, 2)
void conv_gemm_kernel(const float* __restrict__ bias,
                      const float* __restrict__ Berr,
                      float* __restrict__ out) {
    extern __shared__ __align__(16) char smem[];
    const uint32_t sbase = (uint32_t)__cvta_generic_to_shared(smem);

    const int tid  = threadIdx.x;
    const int warp = tid >> 5;
    const int lane = tid & 31;
    const int wm = warp >> 2;
    const int wn = warp & 3;
    const int n0 = blockIdx.x * BN;
    const int m0 = blockIdx.y * BM;
    const int b  = blockIdx.z;

    float acc[4][4][4];
    #pragma unroll
    for (int mf = 0; mf < 4; mf++)
        #pragma unroll
        for (int nf = 0; nf < 4; nf++)
            #pragma unroll
            for (int r = 0; r < 4; r++) acc[mf][nf][r] = 0.f;

    // A: 512 chunks/stage -> 2/thread (rows tid>>2 and +64)
    const int arow0 = tid >> 2;
    const int aseg  = tid & 3;
    size_t abase[2];
    #pragma unroll
    for (int j = 0; j < 2; j++) {
        int m = m0 + arow0 + j * 64;
        if (m >= MM) m = 0;
        int ho = m / WOUT;
        int wo = m - ho * WOUT;
        abase[j] = (((size_t)b * HH + ho) * WWID + wo) * CINC;
    }
    const size_t wbase = (size_t)b * KKTOT * COUTC;

    auto issue_stage = [&](int it, int slot) {
        const int k0 = it * BK;
        const int tap = k0 >> 7;
        const int c0  = k0 & 127;
        const int kh  = tap / 3;
        const int kw  = tap - kh * 3;
        const size_t tapoff = ((size_t)kh * WWID + kw) * CINC + c0;
        const uint32_t a0 = sbase + SMEM_A + slot * A_ST_H * 2;
        const uint32_t b0 = sbase + SMEM_B + slot * B_ST_H * 2;
        #pragma unroll
        for (int j = 0; j < 2; j++) {
            const __half* src = g_Xh + abase[j] + tapoff + aseg * 8;
            cp16(a0 + ((arow0 + j * 64) * A_ROW_H + aseg * 8) * 2, src);
        }
        #pragma unroll
        for (int j = 0; j < 2; j++) {          // B: 32 rows x 16 chunks
            int c = tid + j * 256;
            int row = c >> 4;
            int seg = c & 15;
            const __half* src = g_Wh + wbase + (size_t)(k0 + row) * COUTC + n0 + seg * 8;
            cp16(b0 + (row * B_ROW_H + seg * 8) * 2, src);
        }
    };

    // prologue: 4 stages in flight
    issue_stage(0, 0); cp_commit();
    issue_stage(1, 1); cp_commit();
    issue_stage(2, 2); cp_commit();
    issue_stage(3, 3); cp_commit();

    for (int it = 0; it < NIT; it++) {
        const int s = it % STAGES;
        // group(it) must be complete; up to 3 newer groups may remain in flight
        if (it <= NIT - 4)      cp_wait<3>();
        else if (it == NIT - 3) cp_wait<2>();
        else if (it == NIT - 2) cp_wait<1>();
        else                    cp_wait<0>();
        __syncthreads();
        if (it + 4 < NIT) { issue_stage(it + 4, (it + 4) % STAGES); cp_commit(); }

        const uint32_t aS = sbase + SMEM_A + s * A_ST_H * 2;
        const uint32_t bS = sbase + SMEM_B + s * B_ST_H * 2;
        #pragma unroll
        for (int ks = 0; ks < 2; ks++) {
            // B fragments: 2x ldmatrix.x4.trans -> 4 n8 fragments
            uint32_t bfr[4][2];
            {
                const int brow = ks * 16 + ((lane >> 3) & 1) * 8 + (lane & 7);
                #pragma unroll
                for (int p = 0; p < 2; p++) {
                    const int bcol = wn * 32 + p * 16 + (lane >> 4) * 8;
                    uint32_t r[4];
                    ldmatrix_x4_trans(r, bS + (brow * B_ROW_H + bcol) * 2);
                    bfr[2 * p][0]     = r[0];
                    bfr[2 * p][1]     = r[1];
                    bfr[2 * p + 1][0] = r[2];
                    bfr[2 * p + 1][1] = r[3];
                }
            }
            // A fragments staggered with MMA: load afr[mf+1] before mf's MMAs
            uint32_t afr[4][4];
            const int arL  = wm * 64 + (lane & 15);
            const int acol = ks * 16 + ((lane >> 4) << 3);
            ldmatrix_x4(afr[0], aS + (arL * A_ROW_H + acol) * 2);
            #pragma unroll
            for (int mf = 0; mf < 4; mf++) {
                if (mf < 3)
                    ldmatrix_x4(afr[mf + 1], aS + ((arL + (mf + 1) * 16) * A_ROW_H + acol) * 2);
                #pragma unroll
                for (int nf = 0; nf < 4; nf++)
                    mma16816(acc[mf][nf], afr[mf], bfr[nf]);
            }
        }
    }

    // epilogue: fused noisy bias, f32 stores
    const int gid = lane >> 2;
    const int tg  = lane & 3;
    #pragma unroll
    for (int nf = 0; nf < 4; nf++) {
        const int cc = n0 + wn * 32 + nf * 8 + tg * 2;
        const float mb0 = bias[cc]     * Berr[b * COUTC + cc];
        const float mb1 = bias[cc + 1] * Berr[b * COUTC + cc + 1];
        #pragma unroll
        for (int mf = 0; mf < 4; mf++) {
            const int r0 = m0 + wm * 64 + mf * 16 + gid;
            if (r0 < MM) {
                float2 v = make_float2(acc[mf][nf][0] + mb0, acc[mf][nf][1] + mb1);
                *reinterpret_cast<float2*>(&out[((size_t)b * MM + r0) * NNTOT + cc]) = v;
            }
            const int r1 = r0 + 8;
            if (r1 < MM) {
                float2 v = make_float2(acc[mf][nf][2] + mb0, acc[mf][nf][3] + mb1);
                *reinterpret_cast<float2*>(&out[((size_t)b * MM + r1) * NNTOT + cc]) = v;
            }
        }
    }
}

// ---------------- launch ----------------
extern "C" void kernel_launch(void* const* d_in, const int* in_sizes, int n_in,
                              void* d_out, int out_size) {
    (void)in_sizes; (void)n_in; (void)out_size;
    const float* X    = (const float*)d_in[0];
    const float* W    = (const float*)d_in[1];
    const float* bias = (const float*)d_in[2];
    const float* Werr = (const float*)d_in[3];
    const float* Berr = (const float*)d_in[4];
    float* out = (float*)d_out;

    prep_kernel<<<XBLOCKS + WBLOCKS, 256>>>(X, W, Werr);

    static bool attr_set = false;
    if (!attr_set) {
        cudaFuncSetAttribute(conv_gemm_kernel,
                             cudaFuncAttributeMaxDynamicSharedMemorySize, SMEM_TOTAL);
        attr_set = true;
    }
    dim3 grid(NNTOT / BN, (MM + BM - 1) / BM, BB);   // (2, 31, 64)
    conv_gemm_kernel<<<grid, NTHREADS, SMEM_TOTAL>>>(bias, Berr, out);
}

// round 11
// speedup vs baseline: 1.1363x; 1.1363x over previous
#include <cuda_runtime.h>
#include <cuda_fp16.h>
#include <cstdint>

// ---------------- problem constants ----------------
#define BB    64
#define HH    64
#define WWID  64
#define CINC  128
#define COUTC 256
#define HOUT  62
#define WOUT  62
#define MM    3844
#define KKTOT 1152
#define NNTOT 256

// ---------------- GEMM tiling (R7 champion shape) ----------------
#define BM     128
#define BN     128
#define BK     64
#define NIT    (KKTOT / BK)   // 18
#define STAGES 3
#define NTHREADS 256

// smem (halves): As[s][128][72], Bs[s][64][136]
#define A_ROW_H 72
#define B_ROW_H 136
#define A_ST_H  (BM * A_ROW_H)   // 9216 halves = 18432 B
#define B_ST_H  (BK * B_ROW_H)   // 8704 halves = 17408 B
// barriers: full[3] @0, empty[3] @24; data from 128
#define SMEM_FULL  0
#define SMEM_EMPTY 24
#define SMEM_A     128
#define SMEM_B     (SMEM_A + STAGES * A_ST_H * 2)        // 128 + 55296 = 55424
#define SMEM_TOTAL (SMEM_B + STAGES * B_ST_H * 2)        // 55424 + 52224 = 107648

// ---------------- scratch ----------------
__device__ __half g_Xh[(size_t)BB * HH * WWID * CINC];   // X fp16 NHWC
__device__ __half g_Wh[(size_t)BB * KKTOT * COUTC];      // memW fp16 [b][k][n]

// ---------------- fused prep ----------------
#define XBLOCKS 32768
#define WBLOCKS 18432
__global__ void prep_kernel(const float* __restrict__ X,
                            const float* __restrict__ W,
                            const float* __restrict__ Werr) {
    if (blockIdx.x < XBLOCKS) {
        size_t i = ((size_t)blockIdx.x * blockDim.x + threadIdx.x) * 4;
        float4 v = *reinterpret_cast<const float4*>(X + i);
        __half2 h0 = __floats2half2_rn(v.x, v.y);
        __half2 h1 = __floats2half2_rn(v.z, v.w);
        uint2 o;
        o.x = *reinterpret_cast<uint32_t*>(&h0);
        o.y = *reinterpret_cast<uint32_t*>(&h1);
        *reinterpret_cast<uint2*>(g_Xh + i) = o;
    } else {
        size_t i = ((size_t)(blockIdx.x - XBLOCKS) * blockDim.x + threadIdx.x) * 4;
        size_t wi = i % ((size_t)KKTOT * COUTC);
        float4 w = *reinterpret_cast<const float4*>(W + wi);
        float4 e = *reinterpret_cast<const float4*>(Werr + i);
        __half2 h0 = __floats2half2_rn(w.x * e.x, w.y * e.y);
        __half2 h1 = __floats2half2_rn(w.z * e.z, w.w * e.w);
        uint2 o;
        o.x = *reinterpret_cast<uint32_t*>(&h0);
        o.y = *reinterpret_cast<uint32_t*>(&h1);
        *reinterpret_cast<uint2*>(g_Wh + i) = o;
    }
}

// ---------------- PTX helpers ----------------
__device__ __forceinline__ void cp16(uint32_t dst, const void* src) {
    asm volatile("cp.async.cg.shared.global [%0], [%1], 16;\n" :: "r"(dst), "l"(src));
}
__device__ __forceinline__ void mbar_init(uint32_t a, uint32_t cnt) {
    asm volatile("mbarrier.init.shared.b64 [%0], %1;" :: "r"(a), "r"(cnt) : "memory");
}
__device__ __forceinline__ void mbar_arrive(uint32_t a) {
    asm volatile("mbarrier.arrive.shared.b64 _, [%0];" :: "r"(a) : "memory");
}
// .noinc: async arrival counts against the initialized expected count.
__device__ __forceinline__ void cp_async_mbar_arrive_noinc(uint32_t a) {
    asm volatile("cp.async.mbarrier.arrive.noinc.shared.b64 [%0];" :: "r"(a) : "memory");
}
__device__ __forceinline__ void mbar_wait(uint32_t a, uint32_t parity) {
    asm volatile(
        "{\n\t.reg .pred P1;\n\t"
        "WL_%=:\n\t"
        "mbarrier.try_wait.parity.shared.b64 P1, [%0], %1, 0x989680;\n\t"
        "@P1 bra.uni WD_%=;\n\t"
        "bra.uni WL_%=;\n\t"
        "WD_%=:\n\t}"
        :: "r"(a), "r"(parity) : "memory");
}
__device__ __forceinline__ uint32_t elect_one() {
    uint32_t p;
    asm volatile("{\n\t.reg .pred p;\n\telect.sync _|p, 0xFFFFFFFF;\n\t"
                 "selp.b32 %0, 1, 0, p;\n\t}" : "=r"(p));
    return p;
}
__device__ __forceinline__ void ldmatrix_x4(uint32_t* r, uint32_t addr) {
    asm volatile("ldmatrix.sync.aligned.m8n8.x4.shared.b16 {%0,%1,%2,%3}, [%4];\n"
                 : "=r"(r[0]), "=r"(r[1]), "=r"(r[2]), "=r"(r[3]) : "r"(addr));
}
__device__ __forceinline__ void ldmatrix_x4_trans(uint32_t* r, uint32_t addr) {
    asm volatile("ldmatrix.sync.aligned.m8n8.x4.trans.shared.b16 {%0,%1,%2,%3}, [%4];\n"
                 : "=r"(r[0]), "=r"(r[1]), "=r"(r[2]), "=r"(r[3]) : "r"(addr));
}
__device__ __forceinline__ void mma16816(float* c, const uint32_t* a, const uint32_t* b) {
    asm volatile(
        "mma.sync.aligned.m16n8k16.row.col.f32.f16.f16.f32 "
        "{%0,%1,%2,%3}, {%4,%5,%6,%7}, {%8,%9}, {%0,%1,%2,%3};\n"
        : "+f"(c[0]), "+f"(c[1]), "+f"(c[2]), "+f"(c[3])
        : "r"(a[0]), "r"(a[1]), "r"(a[2]), "r"(a[3]), "r"(b[0]), "r"(b[1]));
}

// ---------------- main GEMM ----------------
// grid (2, 31, 64), 256 threads (2x4 warps, warp tile 64x32)
// 3-slot mbarrier full/empty ring; NO __syncthreads in the mainloop.
__global__ __launch_bounds__(NTHREADS, 2)
void conv_gemm_kernel(const float* __restrict__ bias,
                      const float* __restrict__ Berr,
                      float* __restrict__ out) {
    extern __shared__ __align__(16) char smem[];
    const uint32_t sbase = (uint32_t)__cvta_generic_to_shared(smem);

    const int tid  = threadIdx.x;
    const int warp = tid >> 5;
    const int lane = tid & 31;
    const int wm = warp >> 2;
    const int wn = warp & 3;
    const int n0 = blockIdx.x * BN;
    const int m0 = blockIdx.y * BM;
    const int b  = blockIdx.z;

    // full: 256 async (.noinc) arrivals per phase; empty: 8 warp arrivals
    if (tid == 0) {
        #pragma unroll
        for (int s = 0; s < STAGES; s++) {
            mbar_init(sbase + SMEM_FULL  + s * 8, NTHREADS);
            mbar_init(sbase + SMEM_EMPTY + s * 8, 8);
        }
    }
    __syncthreads();

    float acc[4][4][4];
    #pragma unroll
    for (int mf = 0; mf < 4; mf++)
        #pragma unroll
        for (int nf = 0; nf < 4; nf++)
            #pragma unroll
            for (int r = 0; r < 4; r++) acc[mf][nf][r] = 0.f;

    // A: 128 rows x 8 chunks = 1024 chunks/stage -> 4/thread
    const int arow0 = tid >> 3;
    const int aseg  = tid & 7;
    size_t abase[4];
    #pragma unroll
    for (int j = 0; j < 4; j++) {
        int m = m0 + arow0 + j * 32;
        if (m >= MM) m = 0;
        int ho = m / WOUT;
        int wo = m - ho * WOUT;
        abase[j] = (((size_t)b * HH + ho) * WWID + wo) * CINC;
    }
    const size_t wbase = (size_t)b * KKTOT * COUTC;

    auto issue_stage = [&](int it, int slot) {
        const int k0 = it * BK;
        const int tap = k0 >> 7;
        const int c0  = k0 & 127;
        const int kh  = tap / 3;
        const int kw  = tap - kh * 3;
        const size_t tapoff = ((size_t)kh * WWID + kw) * CINC + c0;
        const uint32_t a0 = sbase + SMEM_A + slot * A_ST_H * 2;
        const uint32_t b0 = sbase + SMEM_B + slot * B_ST_H * 2;
        #pragma unroll
        for (int j = 0; j < 4; j++) {
            const __half* src = g_Xh + abase[j] + tapoff + aseg * 8;
            cp16(a0 + ((arow0 + j * 32) * A_ROW_H + aseg * 8) * 2, src);
        }
        #pragma unroll
        for (int j = 0; j < 4; j++) {          // B: 64 rows x 16 chunks
            int c = tid + j * 256;
            int row = c >> 4;
            int seg = c & 15;
            const __half* src = g_Wh + wbase + (size_t)(k0 + row) * COUTC + n0 + seg * 8;
            cp16(b0 + (row * B_ROW_H + seg * 8) * 2, src);
        }
        cp_async_mbar_arrive_noinc(sbase + SMEM_FULL + slot * 8);
    };

    // prologue: fill slots 0,1 (fresh slots, no empty-wait)
    issue_stage(0, 0);
    issue_stage(1, 1);

    uint32_t fmask = 0, emask = 0;

    for (int it = 0; it < NIT; it++) {
        const int s = it % STAGES;
        // wait data-ready (per-warp; no CTA rendezvous)
        mbar_wait(sbase + SMEM_FULL + s * 8, (fmask >> s) & 1);
        fmask ^= 1u << s;

        const uint32_t aS = sbase + SMEM_A + s * A_ST_H * 2;
        const uint32_t bS = sbase + SMEM_B + s * B_ST_H * 2;
        #pragma unroll
        for (int ks = 0; ks < 4; ks++) {
            uint32_t bfr[4][2];
            {
                const int brow = ks * 16 + ((lane >> 3) & 1) * 8 + (lane & 7);
                #pragma unroll
                for (int p = 0; p < 2; p++) {
                    const int bcol = wn * 32 + p * 16 + (lane >> 4) * 8;
                    uint32_t r[4];
                    ldmatrix_x4_trans(r, bS + (brow * B_ROW_H + bcol) * 2);
                    bfr[2 * p][0]     = r[0];
                    bfr[2 * p][1]     = r[1];
                    bfr[2 * p + 1][0] = r[2];
                    bfr[2 * p + 1][1] = r[3];
                }
            }
            uint32_t afr[4][4];
            const int arL  = wm * 64 + (lane & 15);
            const int acol = ks * 16 + ((lane >> 4) << 3);
            #pragma unroll
            for (int mf = 0; mf < 4; mf++)
                ldmatrix_x4(afr[mf], aS + ((arL + mf * 16) * A_ROW_H + acol) * 2);

            #pragma unroll
            for (int mf = 0; mf < 4; mf++)
                #pragma unroll
                for (int nf = 0; nf < 4; nf++)
                    mma16816(acc[mf][nf], afr[mf], bfr[nf]);
        }

        // release slot s (warp-collective: syncwarp orders all lanes' LDSMs)
        __syncwarp();
        if (elect_one()) mbar_arrive(sbase + SMEM_EMPTY + s * 8);

        // produce stage it+2 into slot (it+2)%3 (= slot consumed at it-1)
        const int nx = it + 2;
        if (nx < NIT) {
            const int sn = nx % STAGES;
            if (nx >= STAGES) {                // slot reused: wait consumers of nx-3
                mbar_wait(sbase + SMEM_EMPTY + sn * 8, (emask >> sn) & 1);
                emask ^= 1u << sn;
            }
            issue_stage(nx, sn);
        }
    }

    // epilogue: fused noisy bias, f32 stores (warp-independent, no sync needed)
    const int gid = lane >> 2;
    const int tg  = lane & 3;
    #pragma unroll
    for (int nf = 0; nf < 4; nf++) {
        const int cc = n0 + wn * 32 + nf * 8 + tg * 2;
        const float mb0 = bias[cc]     * Berr[b * COUTC + cc];
        const float mb1 = bias[cc + 1] * Berr[b * COUTC + cc + 1];
        #pragma unroll
        for (int mf = 0; mf < 4; mf++) {
            const int r0 = m0 + wm * 64 + mf * 16 + gid;
            if (r0 < MM) {
                float2 v = make_float2(acc[mf][nf][0] + mb0, acc[mf][nf][1] + mb1);
                *reinterpret_cast<float2*>(&out[((size_t)b * MM + r0) * NNTOT + cc]) = v;
            }
            const int r1 = r0 + 8;
            if (r1 < MM) {
                float2 v = make_float2(acc[mf][nf][2] + mb0, acc[mf][nf][3] + mb1);
                *reinterpret_cast<float2*>(&out[((size_t)b * MM + r1) * NNTOT + cc]) = v;
            }
        }
    }
}

// ---------------- launch ----------------
extern "C" void kernel_launch(void* const* d_in, const int* in_sizes, int n_in,
                              void* d_out, int out_size) {
    (void)in_sizes; (void)n_in; (void)out_size;
    const float* X    = (const float*)d_in[0];
    const float* W    = (const float*)d_in[1];
    const float* bias = (const float*)d_in[2];
    const float* Werr = (const float*)d_in[3];
    const float* Berr = (const float*)d_in[4];
    float* out = (float*)d_out;

    prep_kernel<<<XBLOCKS + WBLOCKS, 256>>>(X, W, Werr);

    static bool attr_set = false;
    if (!attr_set) {
        cudaFuncSetAttribute(conv_gemm_kernel,
                             cudaFuncAttributeMaxDynamicSharedMemorySize, SMEM_TOTAL);
        attr_set = true;
    }
    dim3 grid(NNTOT / BN, (MM + BM - 1) / BM, BB);   // (2, 31, 64)
    conv_gemm_kernel<<<grid, NTHREADS, SMEM_TOTAL>>>(bias, Berr, out);
}

// round 12
// speedup vs baseline: 1.1364x; 1.0001x over previous
#include <cuda_runtime.h>
#include <cuda_fp16.h>
#include <cstdint>

// ---------------- problem constants ----------------
#define BB    64
#define HH    64
#define WWID  64
#define CINC  128
#define COUTC 256
#define HOUT  62
#define WOUT  62
#define MM    3844
#define KKTOT 1152
#define NNTOT 256

#define BHALF (BB / 2)    // batch half for stream overlap

// ---------------- GEMM tiling (champion shape) ----------------
#define BM     128
#define BN     128
#define BK     64
#define NIT    (KKTOT / BK)   // 18
#define STAGES 3
#define NTHREADS 256

// smem (halves): As[s][128][72], Bs[s][64][136]
#define A_ROW_H 72
#define B_ROW_H 136
#define A_ST_H  (BM * A_ROW_H)   // 9216 halves = 18432 B
#define B_ST_H  (BK * B_ROW_H)   // 8704 halves = 17408 B
#define SMEM_FULL  0
#define SMEM_EMPTY 24
#define SMEM_A     128
#define SMEM_B     (SMEM_A + STAGES * A_ST_H * 2)        // 55424
#define SMEM_TOTAL (SMEM_B + STAGES * B_ST_H * 2)        // 107648

// ---------------- scratch ----------------
__device__ __half g_Xh[(size_t)BB * HH * WWID * CINC];   // X fp16 NHWC
__device__ __half g_Wh[(size_t)BB * KKTOT * COUTC];      // memW fp16 [b][k][n]

// ---------------- prep (per batch half) ----------------
#define XBLOCKS_H 16384   // (32*64*64*128)/4/256
#define WBLOCKS_H 9216    // (32*1152*256)/4/256
__global__ void prep_kernel(const float* __restrict__ X,
                            const float* __restrict__ W,
                            const float* __restrict__ Werr,
                            int bo) {
    if (blockIdx.x < XBLOCKS_H) {
        size_t base = (size_t)bo * HH * WWID * CINC;
        size_t i = base + ((size_t)blockIdx.x * blockDim.x + threadIdx.x) * 4;
        float4 v = *reinterpret_cast<const float4*>(X + i);
        __half2 h0 = __floats2half2_rn(v.x, v.y);
        __half2 h1 = __floats2half2_rn(v.z, v.w);
        uint2 o;
        o.x = *reinterpret_cast<uint32_t*>(&h0);
        o.y = *reinterpret_cast<uint32_t*>(&h1);
        *reinterpret_cast<uint2*>(g_Xh + i) = o;
    } else {
        size_t base = (size_t)bo * KKTOT * COUTC;
        size_t i = base + ((size_t)(blockIdx.x - XBLOCKS_H) * blockDim.x + threadIdx.x) * 4;
        size_t wi = i % ((size_t)KKTOT * COUTC);
        float4 w = *reinterpret_cast<const float4*>(W + wi);
        float4 e = *reinterpret_cast<const float4*>(Werr + i);
        __half2 h0 = __floats2half2_rn(w.x * e.x, w.y * e.y);
        __half2 h1 = __floats2half2_rn(w.z * e.z, w.w * e.w);
        uint2 o;
        o.x = *reinterpret_cast<uint32_t*>(&h0);
        o.y = *reinterpret_cast<uint32_t*>(&h1);
        *reinterpret_cast<uint2*>(g_Wh + i) = o;
    }
}

// ---------------- PTX helpers ----------------
__device__ __forceinline__ void cp16(uint32_t dst, const void* src) {
    asm volatile("cp.async.cg.shared.global [%0], [%1], 16;\n" :: "r"(dst), "l"(src));
}
__device__ __forceinline__ void mbar_init(uint32_t a, uint32_t cnt) {
    asm volatile("mbarrier.init.shared.b64 [%0], %1;" :: "r"(a), "r"(cnt) : "memory");
}
__device__ __forceinline__ void mbar_arrive(uint32_t a) {
    asm volatile("mbarrier.arrive.shared.b64 _, [%0];" :: "r"(a) : "memory");
}
__device__ __forceinline__ void cp_async_mbar_arrive_noinc(uint32_t a) {
    asm volatile("cp.async.mbarrier.arrive.noinc.shared.b64 [%0];" :: "r"(a) : "memory");
}
__device__ __forceinline__ void mbar_wait(uint32_t a, uint32_t parity) {
    asm volatile(
        "{\n\t.reg .pred P1;\n\t"
        "WL_%=:\n\t"
        "mbarrier.try_wait.parity.shared.b64 P1, [%0], %1, 0x989680;\n\t"
        "@P1 bra.uni WD_%=;\n\t"
        "bra.uni WL_%=;\n\t"
        "WD_%=:\n\t}"
        :: "r"(a), "r"(parity) : "memory");
}
__device__ __forceinline__ uint32_t elect_one() {
    uint32_t p;
    asm volatile("{\n\t.reg .pred p;\n\telect.sync _|p, 0xFFFFFFFF;\n\t"
                 "selp.b32 %0, 1, 0, p;\n\t}" : "=r"(p));
    return p;
}
__device__ __forceinline__ void ldmatrix_x4(uint32_t* r, uint32_t addr) {
    asm volatile("ldmatrix.sync.aligned.m8n8.x4.shared.b16 {%0,%1,%2,%3}, [%4];\n"
                 : "=r"(r[0]), "=r"(r[1]), "=r"(r[2]), "=r"(r[3]) : "r"(addr));
}
__device__ __forceinline__ void ldmatrix_x4_trans(uint32_t* r, uint32_t addr) {
    asm volatile("ldmatrix.sync.aligned.m8n8.x4.trans.shared.b16 {%0,%1,%2,%3}, [%4];\n"
                 : "=r"(r[0]), "=r"(r[1]), "=r"(r[2]), "=r"(r[3]) : "r"(addr));
}
__device__ __forceinline__ void mma16816(float* c, const uint32_t* a, const uint32_t* b) {
    asm volatile(
        "mma.sync.aligned.m16n8k16.row.col.f32.f16.f16.f32 "
        "{%0,%1,%2,%3}, {%4,%5,%6,%7}, {%8,%9}, {%0,%1,%2,%3};\n"
        : "+f"(c[0]), "+f"(c[1]), "+f"(c[2]), "+f"(c[3])
        : "r"(a[0]), "r"(a[1]), "r"(a[2]), "r"(a[3]), "r"(b[0]), "r"(b[1]));
}

// ---------------- main GEMM ----------------
// grid (2, 31, 32) per batch half; 256 threads (2x4 warps, warp tile 64x32)
// 3-slot mbarrier full/empty ring; no __syncthreads in mainloop; A-stagger.
__global__ __launch_bounds__(NTHREADS, 2)
void conv_gemm_kernel(const float* __restrict__ bias,
                      const float* __restrict__ Berr,
                      float* __restrict__ out, int bo) {
    extern __shared__ __align__(16) char smem[];
    const uint32_t sbase = (uint32_t)__cvta_generic_to_shared(smem);

    const int tid  = threadIdx.x;
    const int warp = tid >> 5;
    const int lane = tid & 31;
    const int wm = warp >> 2;
    const int wn = warp & 3;
    const int n0 = blockIdx.x * BN;
    const int m0 = blockIdx.y * BM;
    const int b  = blockIdx.z + bo;

    if (tid == 0) {
        #pragma unroll
        for (int s = 0; s < STAGES; s++) {
            mbar_init(sbase + SMEM_FULL  + s * 8, NTHREADS);
            mbar_init(sbase + SMEM_EMPTY + s * 8, 8);
        }
    }
    __syncthreads();

    float acc[4][4][4];
    #pragma unroll
    for (int mf = 0; mf < 4; mf++)
        #pragma unroll
        for (int nf = 0; nf < 4; nf++)
            #pragma unroll
            for (int r = 0; r < 4; r++) acc[mf][nf][r] = 0.f;

    // A: 128 rows x 8 chunks = 1024 chunks/stage -> 4/thread
    const int arow0 = tid >> 3;
    const int aseg  = tid & 7;
    size_t abase[4];
    #pragma unroll
    for (int j = 0; j < 4; j++) {
        int m = m0 + arow0 + j * 32;
        if (m >= MM) m = 0;
        int ho = m / WOUT;
        int wo = m - ho * WOUT;
        abase[j] = (((size_t)b * HH + ho) * WWID + wo) * CINC;
    }
    const size_t wbase = (size_t)b * KKTOT * COUTC;

    auto issue_stage = [&](int it, int slot) {
        const int k0 = it * BK;
        const int tap = k0 >> 7;
        const int c0  = k0 & 127;
        const int kh  = tap / 3;
        const int kw  = tap - kh * 3;
        const size_t tapoff = ((size_t)kh * WWID + kw) * CINC + c0;
        const uint32_t a0 = sbase + SMEM_A + slot * A_ST_H * 2;
        const uint32_t b0 = sbase + SMEM_B + slot * B_ST_H * 2;
        #pragma unroll
        for (int j = 0; j < 4; j++) {
            const __half* src = g_Xh + abase[j] + tapoff + aseg * 8;
            cp16(a0 + ((arow0 + j * 32) * A_ROW_H + aseg * 8) * 2, src);
        }
        #pragma unroll
        for (int j = 0; j < 4; j++) {
            int c = tid + j * 256;
            int row = c >> 4;
            int seg = c & 15;
            const __half* src = g_Wh + wbase + (size_t)(k0 + row) * COUTC + n0 + seg * 8;
            cp16(b0 + (row * B_ROW_H + seg * 8) * 2, src);
        }
        cp_async_mbar_arrive_noinc(sbase + SMEM_FULL + slot * 8);
    };

    issue_stage(0, 0);
    issue_stage(1, 1);

    uint32_t fmask = 0, emask = 0;

    for (int it = 0; it < NIT; it++) {
        const int s = it % STAGES;
        mbar_wait(sbase + SMEM_FULL + s * 8, (fmask >> s) & 1);
        fmask ^= 1u << s;

        const uint32_t aS = sbase + SMEM_A + s * A_ST_H * 2;
        const uint32_t bS = sbase + SMEM_B + s * B_ST_H * 2;
        #pragma unroll
        for (int ks = 0; ks < 4; ks++) {
            uint32_t bfr[4][2];
            {
                const int brow = ks * 16 + ((lane >> 3) & 1) * 8 + (lane & 7);
                #pragma unroll
                for (int p = 0; p < 2; p++) {
                    const int bcol = wn * 32 + p * 16 + (lane >> 4) * 8;
                    uint32_t r[4];
                    ldmatrix_x4_trans(r, bS + (brow * B_ROW_H + bcol) * 2);
                    bfr[2 * p][0]     = r[0];
                    bfr[2 * p][1]     = r[1];
                    bfr[2 * p + 1][0] = r[2];
                    bfr[2 * p + 1][1] = r[3];
                }
            }
            // A staggered with MMA: load afr[mf+1] before mf's MMA quad
            uint32_t afr[4][4];
            const int arL  = wm * 64 + (lane & 15);
            const int acol = ks * 16 + ((lane >> 4) << 3);
            ldmatrix_x4(afr[0], aS + (arL * A_ROW_H + acol) * 2);
            #pragma unroll
            for (int mf = 0; mf < 4; mf++) {
                if (mf < 3)
                    ldmatrix_x4(afr[mf + 1], aS + ((arL + (mf + 1) * 16) * A_ROW_H + acol) * 2);
                #pragma unroll
                for (int nf = 0; nf < 4; nf++)
                    mma16816(acc[mf][nf], afr[mf], bfr[nf]);
            }
        }

        __syncwarp();
        if (elect_one()) mbar_arrive(sbase + SMEM_EMPTY + s * 8);

        const int nx = it + 2;
        if (nx < NIT) {
            const int sn = nx % STAGES;
            if (nx >= STAGES) {
                mbar_wait(sbase + SMEM_EMPTY + sn * 8, (emask >> sn) & 1);
                emask ^= 1u << sn;
            }
            issue_stage(nx, sn);
        }
    }

    // epilogue: fused noisy bias, f32 stores
    const int gid = lane >> 2;
    const int tg  = lane & 3;
    #pragma unroll
    for (int nf = 0; nf < 4; nf++) {
        const int cc = n0 + wn * 32 + nf * 8 + tg * 2;
        const float mb0 = bias[cc]     * Berr[b * COUTC + cc];
        const float mb1 = bias[cc + 1] * Berr[b * COUTC + cc + 1];
        #pragma unroll
        for (int mf = 0; mf < 4; mf++) {
            const int r0 = m0 + wm * 64 + mf * 16 + gid;
            if (r0 < MM) {
                float2 v = make_float2(acc[mf][nf][0] + mb0, acc[mf][nf][1] + mb1);
                *reinterpret_cast<float2*>(&out[((size_t)b * MM + r0) * NNTOT + cc]) = v;
            }
            const int r1 = r0 + 8;
            if (r1 < MM) {
                float2 v = make_float2(acc[mf][nf][2] + mb0, acc[mf][nf][3] + mb1);
                *reinterpret_cast<float2*>(&out[((size_t)b * MM + r1) * NNTOT + cc]) = v;
            }
        }
    }
}

// ---------------- launch: batch-split with stream overlap ----------------
// prep(h0) -> { gemm(h0) on legacy  ||  prep(h1) on s1 } -> gemm(h1) on s1 -> join
extern "C" void kernel_launch(void* const* d_in, const int* in_sizes, int n_in,
                              void* d_out, int out_size) {
    (void)in_sizes; (void)n_in; (void)out_size;
    const float* X    = (const float*)d_in[0];
    const float* W    = (const float*)d_in[1];
    const float* bias = (const float*)d_in[2];
    const float* Werr = (const float*)d_in[3];
    const float* Berr = (const float*)d_in[4];
    float* out = (float*)d_out;

    static cudaStream_t s1;
    static cudaEvent_t e0, e1;
    static bool init_done = false;
    if (!init_done) {
        cudaFuncSetAttribute(conv_gemm_kernel,
                             cudaFuncAttributeMaxDynamicSharedMemorySize, SMEM_TOTAL);
        cudaStreamCreateWithFlags(&s1, cudaStreamNonBlocking);
        cudaEventCreateWithFlags(&e0, cudaEventDisableTiming);
        cudaEventCreateWithFlags(&e1, cudaEventDisableTiming);
        init_done = true;
    }

    const cudaStream_t s0 = 0;   // legacy (capture) stream
    dim3 ggrid(NNTOT / BN, (MM + BM - 1) / BM, BHALF);   // (2, 31, 32)

    // half 0 prep on legacy stream
    prep_kernel<<<XBLOCKS_H + WBLOCKS_H, 256, 0, s0>>>(X, W, Werr, 0);
    cudaEventRecord(e0, s0);
    // fork: half 1 prep on s1, overlapping half-0 GEMM
    cudaStreamWaitEvent(s1, e0, 0);
    prep_kernel<<<XBLOCKS_H + WBLOCKS_H, 256, 0, s1>>>(X, W, Werr, BHALF);

    conv_gemm_kernel<<<ggrid, NTHREADS, SMEM_TOTAL, s0>>>(bias, Berr, out, 0);
    conv_gemm_kernel<<<ggrid, NTHREADS, SMEM_TOTAL, s1>>>(bias, Berr, out, BHALF);

    // join
    cudaEventRecord(e1, s1);
    cudaStreamWaitEvent(s0, e1, 0);
}